// round 1
// baseline (speedup 1.0000x reference)
#include <cuda_runtime.h>
#include <math.h>

// ---------------- problem constants (fixed by the reference) ----------------
#define B_    32
#define N_    577
#define C_    768
#define H_    12
#define D_    64
#define GRID_ 24
#define RAD_  3          // window 7 -> radius 3
#define K_    768        // GEMM K dim (= C)
#define M1_   (B_*N_)    // 18464 rows for both GEMMs

// ---------------- scratch (device globals; no allocations allowed) ----------
__device__ float g_Q[B_*H_*N_*D_];
__device__ float g_K[B_*H_*N_*D_];
__device__ float g_V[B_*H_*N_*D_];
__device__ float g_O[B_*N_*C_];

// ============================================================================
// SGEMM 128x128x8, 256 threads, 8x8 micro-tile per thread.
//   EPILOGUE==0 : C = A @ Wqkv, scatter into g_Q/g_K/g_V as [B,H,N,D]
//   EPILOGUE==1 : C = g_O @ Wproj + bias, write row-major to out
// K is fixed at 768. Ncols is 2304 (qkv) or 768 (proj). M edge is guarded.
// ============================================================================
template <int EPILOGUE>
__global__ __launch_bounds__(256, 2)
void sgemm_kernel(const float* __restrict__ A,
                  const float* __restrict__ Bm,
                  const float* __restrict__ bias,
                  float*       __restrict__ Cout,
                  int M, int Ncols)
{
    __shared__ float As[8][128];   // As[k][m]
    __shared__ float Bs[8][128];   // Bs[k][n]

    const int tid = threadIdx.x;
    const int m0  = blockIdx.y * 128;
    const int n0  = blockIdx.x * 128;

    const float* Aglob = (EPILOGUE == 0) ? A : (const float*)g_O;

    // global load mapping
    const int a_row = tid >> 1;          // 0..127
    const int a_col = (tid & 1) * 4;     // 0 or 4
    const int b_row = tid >> 5;          // 0..7
    const int b_col = (tid & 31) * 4;    // 0..124

    const bool a_valid = (m0 + a_row) < M;
    const float* Aptr = Aglob + (size_t)(m0 + a_row) * K_ + a_col;
    const float* Bptr = Bm + (size_t)b_row * Ncols + (n0 + b_col);

    // compute mapping: thread (ty,tx) owns rows ty*8..+7, cols tx*8..+7
    const int ty = tid >> 4;
    const int tx = tid & 15;

    float acc[8][8];
#pragma unroll
    for (int i = 0; i < 8; i++)
#pragma unroll
        for (int j = 0; j < 8; j++) acc[i][j] = 0.f;

    for (int k0 = 0; k0 < K_; k0 += 8) {
        float4 av = a_valid ? *(const float4*)(Aptr + k0)
                            : make_float4(0.f, 0.f, 0.f, 0.f);
        float4 bv = *(const float4*)(Bptr + (size_t)k0 * Ncols);

        __syncthreads();   // previous iteration's compute done
        As[a_col + 0][a_row] = av.x;
        As[a_col + 1][a_row] = av.y;
        As[a_col + 2][a_row] = av.z;
        As[a_col + 3][a_row] = av.w;
        *(float4*)&Bs[b_row][b_col] = bv;
        __syncthreads();

#pragma unroll
        for (int k = 0; k < 8; k++) {
            float af[8], bf[8];
            *(float4*)&af[0] = *(const float4*)&As[k][ty * 8];
            *(float4*)&af[4] = *(const float4*)&As[k][ty * 8 + 4];
            *(float4*)&bf[0] = *(const float4*)&Bs[k][tx * 8];
            *(float4*)&bf[4] = *(const float4*)&Bs[k][tx * 8 + 4];
#pragma unroll
            for (int i = 0; i < 8; i++)
#pragma unroll
                for (int j = 0; j < 8; j++)
                    acc[i][j] = fmaf(af[i], bf[j], acc[i][j]);
        }
    }

    // ---------------- epilogue ----------------
    int   mrow[8], bb[8], nn[8];
    bool  vm[8];
#pragma unroll
    for (int i = 0; i < 8; i++) {
        mrow[i] = m0 + ty * 8 + i;
        vm[i]   = mrow[i] < M;
        bb[i]   = mrow[i] / N_;
        nn[i]   = mrow[i] % N_;
    }

    if (EPILOGUE == 0) {
#pragma unroll
        for (int j = 0; j < 8; j++) {
            const int n     = n0 + tx * 8 + j;
            const int which = n / C_;            // 0=q 1=k 2=v
            const int hh    = (n % C_) >> 6;     // head
            const int dd    = n & 63;            // dim within head
            float* base = (which == 0) ? g_Q : (which == 1) ? g_K : g_V;
#pragma unroll
            for (int i = 0; i < 8; i++) {
                if (vm[i]) {
                    base[(((size_t)bb[i] * H_ + hh) * N_ + nn[i]) * D_ + dd] = acc[i][j];
                }
            }
        }
    } else {
#pragma unroll
        for (int j = 0; j < 8; j++) {
            const int n  = n0 + tx * 8 + j;
            const float bj = bias[n];
#pragma unroll
            for (int i = 0; i < 8; i++) {
                if (vm[i]) {
                    Cout[(size_t)mrow[i] * C_ + n] = acc[i][j] + bj;
                }
            }
        }
    }
}

// ============================================================================
// Sparse local attention. One warp per (b, h, query).
// Non-CLS query (patch r,c): keys = {0} U { 1 + r'*24 + c' : |dr|<=3,|dc|<=3 }
// CLS query (n==0): keys = all 577.
// Warp-reduce QK (coalesced K loads), shared score buffer, per-lane AV.
// ============================================================================
__global__ __launch_bounds__(128)
void attn_kernel()
{
    __shared__ float sc[4][N_];
    __shared__ int   kid[4][N_];

    const int warp = threadIdx.x >> 5;
    const int lane = threadIdx.x & 31;
    const int w    = blockIdx.x * 4 + warp;
    if (w >= B_ * H_ * N_) return;

    const int b   = w / (H_ * N_);
    const int rem = w % (H_ * N_);
    const int h   = rem / N_;
    const int n   = rem % N_;

    const size_t head_off = ((size_t)b * H_ + h) * N_ * D_;
    const float* qp    = g_Q + head_off + (size_t)n * D_;
    const float* Kbase = g_K + head_off;
    const float* Vbase = g_V + head_off;

    const float q0 = qp[lane];
    const float q1 = qp[lane + 32];
    const float scale = 0.125f;   // 1/sqrt(64)

    int cnt = 0;

    if (n == 0) {
        // CLS attends to everything
        for (int j = 0; j < N_; j++) {
            const float* kp = Kbase + (size_t)j * D_;
            float s = q0 * kp[lane] + q1 * kp[lane + 32];
#pragma unroll
            for (int off = 16; off; off >>= 1)
                s += __shfl_xor_sync(0xffffffffu, s, off);
            if (lane == 0) { sc[warp][cnt] = s * scale; kid[warp][cnt] = j; }
            cnt++;
        }
    } else {
        const int pi = n - 1;
        const int r  = pi / GRID_;
        const int c  = pi % GRID_;
        // CLS key first
        {
            float s = q0 * Kbase[lane] + q1 * Kbase[lane + 32];
#pragma unroll
            for (int off = 16; off; off >>= 1)
                s += __shfl_xor_sync(0xffffffffu, s, off);
            if (lane == 0) { sc[warp][0] = s * scale; kid[warp][0] = 0; }
            cnt = 1;
        }
        const int r0c = (r - RAD_ < 0) ? 0 : r - RAD_;
        const int r1c = (r + RAD_ > GRID_ - 1) ? GRID_ - 1 : r + RAD_;
        const int c0c = (c - RAD_ < 0) ? 0 : c - RAD_;
        const int c1c = (c + RAD_ > GRID_ - 1) ? GRID_ - 1 : c + RAD_;
        for (int rr = r0c; rr <= r1c; rr++) {
            for (int cc = c0c; cc <= c1c; cc++) {
                const int j = 1 + rr * GRID_ + cc;
                const float* kp = Kbase + (size_t)j * D_;
                float s = q0 * kp[lane] + q1 * kp[lane + 32];
#pragma unroll
                for (int off = 16; off; off >>= 1)
                    s += __shfl_xor_sync(0xffffffffu, s, off);
                if (lane == 0) { sc[warp][cnt] = s * scale; kid[warp][cnt] = j; }
                cnt++;
            }
        }
    }
    __syncwarp();

    // softmax over cnt scores
    float mx = -1e30f;
    for (int i = lane; i < cnt; i += 32) mx = fmaxf(mx, sc[warp][i]);
#pragma unroll
    for (int off = 16; off; off >>= 1)
        mx = fmaxf(mx, __shfl_xor_sync(0xffffffffu, mx, off));

    float sum = 0.f;
    for (int i = lane; i < cnt; i += 32) {
        float e = expf(sc[warp][i] - mx);
        sc[warp][i] = e;
        sum += e;
    }
#pragma unroll
    for (int off = 16; off; off >>= 1)
        sum += __shfl_xor_sync(0xffffffffu, sum, off);
    const float inv = 1.0f / sum;
    __syncwarp();

    // AV: lane owns dims lane and lane+32
    float a0 = 0.f, a1 = 0.f;
    for (int i = 0; i < cnt; i++) {
        const float p = sc[warp][i];
        const float* vp = Vbase + (size_t)kid[warp][i] * D_;
        a0 = fmaf(p, vp[lane],      a0);
        a1 = fmaf(p, vp[lane + 32], a1);
    }
    a0 *= inv;
    a1 *= inv;

    // O[b][n][h*64+d]
    float* op = g_O + ((size_t)b * N_ + n) * C_ + h * D_;
    op[lane]      = a0;
    op[lane + 32] = a1;
}

// ============================================================================
// launch
// ============================================================================
extern "C" void kernel_launch(void* const* d_in, const int* in_sizes, int n_in,
                              void* d_out, int out_size)
{
    const float* x     = (const float*)d_in[0];   // [B,N,C]
    const float* Wqkv  = (const float*)d_in[1];   // [C,3C]
    const float* Wproj = (const float*)d_in[2];   // [C,C]
    const float* bproj = (const float*)d_in[3];   // [C]
    // d_in[4] = mask : not needed, reconstructed analytically
    float* out = (float*)d_out;                   // [B,N,C]

    // 1) QKV projection + scatter to [B,H,N,D]
    {
        dim3 grid(3 * C_ / 128, (M1_ + 127) / 128);   // 18 x 145
        sgemm_kernel<0><<<grid, 256>>>(x, Wqkv, nullptr, nullptr, M1_, 3 * C_);
    }

    // 2) sparse local attention -> g_O [B,N,C]
    {
        const int total_warps = B_ * H_ * N_;
        attn_kernel<<<(total_warps + 3) / 4, 128>>>();
    }

    // 3) output projection + bias
    {
        dim3 grid(C_ / 128, (M1_ + 127) / 128);       // 6 x 145
        sgemm_kernel<1><<<grid, 256>>>(nullptr, Wproj, bproj, out, M1_, C_);
    }
}

// round 3
// speedup vs baseline: 1.9725x; 1.9725x over previous
#include <cuda_runtime.h>
#include <cuda_bf16.h>
#include <cstdint>
#include <math.h>

// ---------------- problem constants ----------------
#define B_    32
#define N_    577
#define C_    768
#define H_    12
#define D_    64
#define GRID_ 24
#define RAD_  3
#define K_    768
#define M_    (B_*N_)      // 18464
#define MT_   145          // ceil(M/128)
#define MPAD_ (MT_*128)    // 18560

// ---------------- device-global scratch (no allocations allowed) ------------
__device__ __nv_bfloat16 g_xhi[MPAD_*K_];
__device__ __nv_bfloat16 g_xlo[MPAD_*K_];
__device__ __nv_bfloat16 g_Whi[3*C_*K_];   // Wqkv^T  [2304,768]
__device__ __nv_bfloat16 g_Wlo[3*C_*K_];
__device__ __nv_bfloat16 g_Phi[C_*K_];     // Wproj^T [768,768]
__device__ __nv_bfloat16 g_Plo[C_*K_];
__device__ float         g_QKV[(size_t)M_*3*C_];      // qkv rows [m, 2304]
__device__ __nv_bfloat16 g_Ohi[MPAD_*C_];
__device__ __nv_bfloat16 g_Olo[MPAD_*C_];

// ---------------- PTX helpers ----------------
__device__ __forceinline__ uint32_t smem_u32(const void* p) {
    uint32_t a;
    asm("{ .reg .u64 t; cvta.to.shared.u64 t, %1; cvt.u32.u64 %0, t; }" : "=r"(a) : "l"(p));
    return a;
}
__device__ __forceinline__ void cp_async16(uint32_t dst, const void* src) {
    asm volatile("cp.async.cg.shared.global [%0], [%1], 16;" :: "r"(dst), "l"(src));
}
__device__ __forceinline__ void cp_commit() {
    asm volatile("cp.async.commit_group;");
}
template <int NN>
__device__ __forceinline__ void cp_wait() {
    asm volatile("cp.async.wait_group %0;" :: "n"(NN));
}
__device__ __forceinline__ void ldmatrix_x4(uint32_t& r0, uint32_t& r1,
                                            uint32_t& r2, uint32_t& r3, uint32_t addr) {
    asm volatile("ldmatrix.sync.aligned.m8n8.x4.shared.b16 {%0,%1,%2,%3}, [%4];"
                 : "=r"(r0), "=r"(r1), "=r"(r2), "=r"(r3) : "r"(addr));
}
__device__ __forceinline__ void mma_bf16(float* c, const uint32_t* a,
                                         uint32_t b0, uint32_t b1) {
    asm volatile(
        "mma.sync.aligned.m16n8k16.row.col.f32.bf16.bf16.f32 "
        "{%0,%1,%2,%3}, {%4,%5,%6,%7}, {%8,%9}, {%0,%1,%2,%3};"
        : "+f"(c[0]), "+f"(c[1]), "+f"(c[2]), "+f"(c[3])
        : "r"(a[0]), "r"(a[1]), "r"(a[2]), "r"(a[3]), "r"(b0), "r"(b1));
}

// ============================================================================
// conversion kernels
// ============================================================================
__global__ void conv_x_kernel(const float* __restrict__ x) {
    size_t idx = (size_t)blockIdx.x * 256 + threadIdx.x;
    if (idx >= (size_t)MPAD_ * K_) return;
    size_t m = idx / K_;
    if (m < M_) {
        float a = x[idx];
        __nv_bfloat16 hi = __float2bfloat16(a);
        __nv_bfloat16 lo = __float2bfloat16(a - __bfloat162float(hi));
        g_xhi[idx] = hi;
        g_xlo[idx] = lo;
    } else {
        g_xhi[idx] = __float2bfloat16(0.f);
        g_xlo[idx] = __float2bfloat16(0.f);
        g_Ohi[idx] = __float2bfloat16(0.f);   // same index space [MPAD*768]
        g_Olo[idx] = __float2bfloat16(0.f);
    }
}

// transpose-convert: W [K_, Ncols] fp32 -> T [Ncols, K_] bf16 hi/lo
__global__ void conv_wT_kernel(const float* __restrict__ W,
                               __nv_bfloat16* __restrict__ Thi,
                               __nv_bfloat16* __restrict__ Tlo, int Ncols) {
    __shared__ float t[32][33];
    const int kc = blockIdx.y * 32;
    const int nc = blockIdx.x * 32;
    const int tx = threadIdx.x & 31;
    const int ty = threadIdx.x >> 5;
    for (int i = ty; i < 32; i += 8)
        t[i][tx] = W[(size_t)(kc + i) * Ncols + nc + tx];
    __syncthreads();
    for (int i = ty; i < 32; i += 8) {
        float a = t[tx][i];
        __nv_bfloat16 hi = __float2bfloat16(a);
        __nv_bfloat16 lo = __float2bfloat16(a - __bfloat162float(hi));
        size_t o = (size_t)(nc + i) * K_ + kc + tx;
        Thi[o] = hi;
        Tlo[o] = lo;
    }
}

// ============================================================================
// split-bf16 HMMA GEMM: C[M,Ncols] = A @ B^T (+bias)
// A: [MPAD,K] bf16 hi/lo, B: [Ncols,K] bf16 hi/lo.
// 128x128x64 tiles, 256 threads (8 warps, 4x2), cp.async double buffer.
// SMEM row = 128B (64 bf16), swizzle: 16B-chunk ^= (row & 7).
// ============================================================================
#define NCHUNK   (K_/64)         // 12
#define STAGE_B  (4*128*128)     // 64KB: Ahi,Alo,Bhi,Blo each 128x128B
#define TILE_B   (128*128)       // 16KB

__global__ __launch_bounds__(256, 1)
void hmma_gemm_kernel(const __nv_bfloat16* __restrict__ Ahi,
                      const __nv_bfloat16* __restrict__ Alo,
                      const __nv_bfloat16* __restrict__ Bhi,
                      const __nv_bfloat16* __restrict__ Blo,
                      const float* __restrict__ bias,
                      float* __restrict__ Cout,
                      int Ncols, int Mrows)
{
    extern __shared__ unsigned char smem[];
    const uint32_t s_base = smem_u32(smem);

    const int tid   = threadIdx.x;
    const int wid   = tid >> 5;
    const int lane  = tid & 31;
    const int m0    = blockIdx.y * 128;
    const int n0    = blockIdx.x * 128;
    const int wm    = (wid >> 1) * 32;   // warp m offset 0/32/64/96
    const int wn    = (wid & 1) * 64;    // warp n offset 0/64

    // ---- cp.async stage loader ----
    const int lr = tid >> 3;   // 0..31 (row group)
    const int lc = tid & 7;    // 16B chunk
    auto load_stage = [&](int st, int kc) {
        const uint32_t sb = s_base + st * STAGE_B;
        const int k0 = kc * 64 + lc * 8;
#pragma unroll
        for (int i = 0; i < 4; i++) {
            const int row = lr + i * 32;
            const uint32_t so = row * 128 + ((lc ^ (row & 7)) << 4);
            const size_t ga = (size_t)(m0 + row) * K_ + k0;
            const size_t gb = (size_t)(n0 + row) * K_ + k0;
            cp_async16(sb + so,              Ahi + ga);
            cp_async16(sb + TILE_B + so,     Alo + ga);
            cp_async16(sb + 2*TILE_B + so,   Bhi + gb);
            cp_async16(sb + 3*TILE_B + so,   Blo + gb);
        }
    };

    float acc[2][8][4];
#pragma unroll
    for (int i = 0; i < 2; i++)
#pragma unroll
        for (int j = 0; j < 8; j++)
#pragma unroll
            for (int v = 0; v < 4; v++) acc[i][j][v] = 0.f;

    load_stage(0, 0);
    cp_commit();

    // ldmatrix lane address components (constant across chunks)
    const int a_row = (lane & 15);        // + mbase
    const int a_chi = (lane >> 4);        // chunk bit
    const int b_row = (lane & 7) + ((lane >> 4) << 3);
    const int b_chi = (lane >> 3) & 1;

    for (int kc = 0; kc < NCHUNK; kc++) {
        if (kc + 1 < NCHUNK) {
            load_stage((kc + 1) & 1, kc + 1);
            cp_commit();
            cp_wait<1>();
        } else {
            cp_wait<0>();
        }
        __syncthreads();

        const uint32_t sb   = s_base + (kc & 1) * STAGE_B;
        const uint32_t sAhi = sb;
        const uint32_t sAlo = sb + TILE_B;
        const uint32_t sBhi = sb + 2*TILE_B;
        const uint32_t sBlo = sb + 3*TILE_B;

#pragma unroll
        for (int s = 0; s < 4; s++) {
            uint32_t fah[2][4], fal[2][4];
#pragma unroll
            for (int mi = 0; mi < 2; mi++) {
                const int row = wm + mi * 16 + a_row;
                const int ch  = (2 * s + a_chi) ^ (row & 7);
                const uint32_t off = row * 128 + (ch << 4);
                ldmatrix_x4(fah[mi][0], fah[mi][1], fah[mi][2], fah[mi][3], sAhi + off);
                ldmatrix_x4(fal[mi][0], fal[mi][1], fal[mi][2], fal[mi][3], sAlo + off);
            }
            uint32_t fbh[4][4], fbl[4][4];
#pragma unroll
            for (int ng = 0; ng < 4; ng++) {
                const int row = wn + ng * 16 + b_row;
                const int ch  = (2 * s + b_chi) ^ (row & 7);
                const uint32_t off = row * 128 + (ch << 4);
                ldmatrix_x4(fbh[ng][0], fbh[ng][1], fbh[ng][2], fbh[ng][3], sBhi + off);
                ldmatrix_x4(fbl[ng][0], fbl[ng][1], fbl[ng][2], fbl[ng][3], sBlo + off);
            }
#pragma unroll
            for (int mi = 0; mi < 2; mi++) {
#pragma unroll
                for (int ng = 0; ng < 4; ng++) {
#pragma unroll
                    for (int hh = 0; hh < 2; hh++) {
                        float* c = acc[mi][ng * 2 + hh];
                        const uint32_t bh0 = fbh[ng][hh * 2], bh1 = fbh[ng][hh * 2 + 1];
                        const uint32_t bl0 = fbl[ng][hh * 2], bl1 = fbl[ng][hh * 2 + 1];
                        mma_bf16(c, fah[mi], bh0, bh1);
                        mma_bf16(c, fah[mi], bl0, bl1);
                        mma_bf16(c, fal[mi], bh0, bh1);
                    }
                }
            }
        }
        __syncthreads();
    }

    // ---- epilogue: direct global stores (float2 per mma tile row) ----
#pragma unroll
    for (int ni = 0; ni < 8; ni++) {
        const int col = n0 + wn + ni * 8 + (lane & 3) * 2;
        const float bx = bias ? bias[col]     : 0.f;
        const float by = bias ? bias[col + 1] : 0.f;
#pragma unroll
        for (int mi = 0; mi < 2; mi++) {
            const int r0 = m0 + wm + mi * 16 + (lane >> 2);
            if (r0 < Mrows) {
                float2 v = make_float2(acc[mi][ni][0] + bx, acc[mi][ni][1] + by);
                *(float2*)(Cout + (size_t)r0 * Ncols + col) = v;
            }
            const int r1 = r0 + 8;
            if (r1 < Mrows) {
                float2 v = make_float2(acc[mi][ni][2] + bx, acc[mi][ni][3] + by);
                *(float2*)(Cout + (size_t)r1 * Ncols + col) = v;
            }
        }
    }
}

// ============================================================================
// sparse local attention: one warp per (b,h,query); reads g_QKV, writes O hi/lo
// ============================================================================
__global__ __launch_bounds__(128)
void attn_kernel()
{
    __shared__ float sc[4][N_];
    __shared__ int   kid[4][N_];

    const int warp = threadIdx.x >> 5;
    const int lane = threadIdx.x & 31;
    const int w    = blockIdx.x * 4 + warp;
    if (w >= B_ * H_ * N_) return;

    const int b   = w / (H_ * N_);
    const int rem = w % (H_ * N_);
    const int h   = rem / N_;
    const int n   = rem % N_;

    const size_t rowm = (size_t)b * N_ + n;
    const float* qp = g_QKV + rowm * (3 * C_) + h * D_;
    const float q0 = qp[lane];
    const float q1 = qp[lane + 32];
    const float scale = 0.125f;

    const size_t krow0 = (size_t)b * N_ * (3 * C_);
    const int koff = C_ + h * D_;
    const int voff = 2 * C_ + h * D_;

    int cnt = 0;

    if (n == 0) {
        for (int j = 0; j < N_; j++) {
            const float* kp = g_QKV + krow0 + (size_t)j * (3 * C_) + koff;
            float s = q0 * kp[lane] + q1 * kp[lane + 32];
#pragma unroll
            for (int off = 16; off; off >>= 1)
                s += __shfl_xor_sync(0xffffffffu, s, off);
            if (lane == 0) { sc[warp][cnt] = s * scale; kid[warp][cnt] = j; }
            cnt++;
        }
    } else {
        const int pi = n - 1;
        const int r  = pi / GRID_;
        const int c  = pi % GRID_;
        {
            const float* kp = g_QKV + krow0 + koff;
            float s = q0 * kp[lane] + q1 * kp[lane + 32];
#pragma unroll
            for (int off = 16; off; off >>= 1)
                s += __shfl_xor_sync(0xffffffffu, s, off);
            if (lane == 0) { sc[warp][0] = s * scale; kid[warp][0] = 0; }
            cnt = 1;
        }
        const int r0c = (r - RAD_ < 0) ? 0 : r - RAD_;
        const int r1c = (r + RAD_ > GRID_ - 1) ? GRID_ - 1 : r + RAD_;
        const int c0c = (c - RAD_ < 0) ? 0 : c - RAD_;
        const int c1c = (c + RAD_ > GRID_ - 1) ? GRID_ - 1 : c + RAD_;
        for (int rr = r0c; rr <= r1c; rr++) {
            for (int cc = c0c; cc <= c1c; cc++) {
                const int j = 1 + rr * GRID_ + cc;
                const float* kp = g_QKV + krow0 + (size_t)j * (3 * C_) + koff;
                float s = q0 * kp[lane] + q1 * kp[lane + 32];
#pragma unroll
                for (int off = 16; off; off >>= 1)
                    s += __shfl_xor_sync(0xffffffffu, s, off);
                if (lane == 0) { sc[warp][cnt] = s * scale; kid[warp][cnt] = j; }
                cnt++;
            }
        }
    }
    __syncwarp();

    float mx = -1e30f;
    for (int i = lane; i < cnt; i += 32) mx = fmaxf(mx, sc[warp][i]);
#pragma unroll
    for (int off = 16; off; off >>= 1)
        mx = fmaxf(mx, __shfl_xor_sync(0xffffffffu, mx, off));

    float sum = 0.f;
    for (int i = lane; i < cnt; i += 32) {
        float e = expf(sc[warp][i] - mx);
        sc[warp][i] = e;
        sum += e;
    }
#pragma unroll
    for (int off = 16; off; off >>= 1)
        sum += __shfl_xor_sync(0xffffffffu, sum, off);
    const float inv = 1.0f / sum;
    __syncwarp();

    float a0 = 0.f, a1 = 0.f;
    for (int i = 0; i < cnt; i++) {
        const float p = sc[warp][i];
        const float* vp = g_QKV + krow0 + (size_t)kid[warp][i] * (3 * C_) + voff;
        a0 = fmaf(p, vp[lane],      a0);
        a1 = fmaf(p, vp[lane + 32], a1);
    }
    a0 *= inv;
    a1 *= inv;

    const size_t o = rowm * C_ + h * D_;
    __nv_bfloat16 h0 = __float2bfloat16(a0);
    __nv_bfloat16 h1 = __float2bfloat16(a1);
    g_Ohi[o + lane]      = h0;
    g_Olo[o + lane]      = __float2bfloat16(a0 - __bfloat162float(h0));
    g_Ohi[o + lane + 32] = h1;
    g_Olo[o + lane + 32] = __float2bfloat16(a1 - __bfloat162float(h1));
}

// ============================================================================
// launch
// ============================================================================
extern "C" void kernel_launch(void* const* d_in, const int* in_sizes, int n_in,
                              void* d_out, int out_size)
{
    const float* x     = (const float*)d_in[0];   // [B,N,C]
    const float* Wqkv  = (const float*)d_in[1];   // [C,3C]
    const float* Wproj = (const float*)d_in[2];   // [C,C]
    const float* bproj = (const float*)d_in[3];   // [C]
    float* out = (float*)d_out;                   // [B,N,C]

    static int smem_set = 0;
    if (!smem_set) {
        cudaFuncSetAttribute(hmma_gemm_kernel,
                             cudaFuncAttributeMaxDynamicSharedMemorySize, 2 * STAGE_B);
        smem_set = 1;
    }

    // 0) conversions
    {
        size_t total = (size_t)MPAD_ * K_;
        conv_x_kernel<<<(unsigned)((total + 255) / 256), 256>>>(x);
        __nv_bfloat16 *whi, *wlo, *phi, *plo;
        cudaGetSymbolAddress((void**)&whi, g_Whi);
        cudaGetSymbolAddress((void**)&wlo, g_Wlo);
        cudaGetSymbolAddress((void**)&phi, g_Phi);
        cudaGetSymbolAddress((void**)&plo, g_Plo);
        conv_wT_kernel<<<dim3(3 * C_ / 32, K_ / 32), 256>>>(Wqkv, whi, wlo, 3 * C_);
        conv_wT_kernel<<<dim3(C_ / 32, K_ / 32), 256>>>(Wproj, phi, plo, C_);
    }

    __nv_bfloat16 *xhi, *xlo, *whi, *wlo, *phi, *plo, *ohi, *olo;
    float* qkv;
    cudaGetSymbolAddress((void**)&xhi, g_xhi);
    cudaGetSymbolAddress((void**)&xlo, g_xlo);
    cudaGetSymbolAddress((void**)&whi, g_Whi);
    cudaGetSymbolAddress((void**)&wlo, g_Wlo);
    cudaGetSymbolAddress((void**)&phi, g_Phi);
    cudaGetSymbolAddress((void**)&plo, g_Plo);
    cudaGetSymbolAddress((void**)&ohi, g_Ohi);
    cudaGetSymbolAddress((void**)&olo, g_Olo);
    cudaGetSymbolAddress((void**)&qkv, g_QKV);

    // 1) QKV GEMM: [M,768] @ [2304,768]^T -> g_QKV
    hmma_gemm_kernel<<<dim3(3 * C_ / 128, MT_), 256, 2 * STAGE_B>>>(
        xhi, xlo, whi, wlo, nullptr, qkv, 3 * C_, M_);

    // 2) sparse local attention -> O hi/lo
    {
        const int total_warps = B_ * H_ * N_;
        attn_kernel<<<(total_warps + 3) / 4, 128>>>();
    }

    // 3) proj GEMM: [M,768] @ [768,768]^T + bias -> out
    hmma_gemm_kernel<<<dim3(C_ / 128, MT_), 256, 2 * STAGE_B>>>(
        ohi, olo, phi, plo, bproj, out, C_, M_);
}